// round 13
// baseline (speedup 1.0000x reference)
#include <cuda_runtime.h>
#include <cuda_bf16.h>
#include <cstdint>

// LengthRegulator. Live work (predictor is dead code in the reference):
//   cum = cumsum(target_durations, axis=1)
//   padded[b,f,:] = (f < cum[b,-1]) ? x[b, upper_bound(cum[b], f), :] : 0
//   durations_out = target_durations
// B=8, T=1024, D=1024, F=8192. Output fp32: [B*F*D padded][B*T durations].
//
// R13: (a) PDL trigger moved AFTER the g_tok scatter (R12 triggered at entry,
// which does not order the scatter writes before the secondary's gridDepSync
// -> latent race). (b) Token fetch via lane 0-7 loads + shfl broadcast:
// 8 LDG/warp instead of 8 LDG/thread, halving expand's L1 wavefront load.

#define LR_B 8
#define LR_T 1024
#define LR_D 1024
#define LR_F 8192
#define LR_V4 (LR_D / 4)          // 256 float4 per row
#define FRAMES 8                  // frames per expand block (uniform)
#define SLABS (LR_F / FRAMES)     // 1024 slabs per batch
#define NTHR 256

__device__ int g_tok[LR_B * LR_F];   // frame -> token (-1 = invalid)

// ---------------------------------------------------------------------------
// Kernel 1: per-batch scan + frame->token scatter + durations pass-through.
// 8 blocks x 256 threads, 4 tokens/thread via int4.
// ---------------------------------------------------------------------------
__global__ void __launch_bounds__(NTHR)
lr_scan_kernel(const int* __restrict__ dur, float* __restrict__ dur_out) {
    const int b   = blockIdx.x;
    const int tid = threadIdx.x;
    __shared__ int warp_sums[8];
    __shared__ int s_total;

    const int4 dv = __ldg(reinterpret_cast<const int4*>(dur + b * LR_T) + tid);
    const int s0 = dv.x;
    const int s1 = s0 + dv.y;
    const int s2 = s1 + dv.z;
    const int s3 = s2 + dv.w;

    const int lane = tid & 31, wid = tid >> 5;
    int s = s3;
    #pragma unroll
    for (int o = 1; o < 32; o <<= 1) {
        int u = __shfl_up_sync(0xFFFFFFFFu, s, o);
        if (lane >= o) s += u;
    }
    if (lane == 31) warp_sums[wid] = s;
    __syncthreads();
    if (wid == 0 && lane < 8) {
        int ws = warp_sums[lane];
        #pragma unroll
        for (int o = 1; o < 8; o <<= 1) {
            int u = __shfl_up_sync(0xFFu, ws, o);
            if (lane >= o) ws += u;
        }
        warp_sums[lane] = ws;
    }
    __syncthreads();
    const int base = ((wid > 0) ? warp_sums[wid - 1] : 0) + s - s3;  // exclusive
    if (tid == NTHR - 1) s_total = base + s3;
    __syncthreads();
    const int total = s_total;

    if (dur_out) {
        float4 fo = make_float4((float)dv.x, (float)dv.y,
                                (float)dv.z, (float)dv.w);
        reinterpret_cast<float4*>(dur_out + b * LR_T)[tid] = fo;
    }

    int* tokb = &g_tok[b * LR_F];
    for (int f = total + tid; f < LR_F; f += NTHR) tokb[f] = -1;

    const int t0 = tid * 4;
    int st = base;
    #pragma unroll
    for (int k = 0; k < 4; ++k) {
        const int en = base + ((k == 0) ? s0 : (k == 1) ? s1 : (k == 2) ? s2 : s3);
        for (int f = st; f < en; ++f) tokb[f] = t0 + k;
        st = en;
    }

#if __CUDA_ARCH__ >= 900
    // Trigger AFTER all g_tok writes: orders them before the secondary
    // grid's cudaGridDependencySynchronize.
    cudaTriggerProgrammaticLaunchCompletion();
#endif
}

// ---------------------------------------------------------------------------
// Kernel 2: balanced expand, dedup'd independent loads, shuffle-broadcast
// token fetch.
// ---------------------------------------------------------------------------
__global__ void __launch_bounds__(LR_V4)
lr_expand_kernel(const float* __restrict__ x, float* __restrict__ out) {
#if __CUDA_ARCH__ >= 900
    cudaGridDependencySynchronize();  // wait for scan's triggered writes
#endif
    const int b    = blockIdx.y;
    const int f0   = blockIdx.x * FRAMES;
    const int i    = threadIdx.x;  // 0..255
    const int lane = i & 31;

    // Token fetch: 8 LDG per WARP (lanes 0-7), broadcast via shuffles.
    int myTok = 0;
    if (lane < FRAMES) myTok = __ldcg(&g_tok[b * LR_F + f0 + lane]);
    int tok[FRAMES];
    #pragma unroll
    for (int j = 0; j < FRAMES; ++j)
        tok[j] = __shfl_sync(0xFFFFFFFFu, myTok, j);

    const float4* x4 = reinterpret_cast<const float4*>(x) +
                       (size_t)b * LR_T * LR_V4 + i;
    float4* o = reinterpret_cast<float4*>(out) +
                ((size_t)b * LR_F + f0) * LR_V4 + i;

    const float4 z = make_float4(0.f, 0.f, 0.f, 0.f);

    bool lead[FRAMES];
    lead[0] = true;
    #pragma unroll
    for (int j = 1; j < FRAMES; ++j) lead[j] = (tok[j] != tok[j - 1]);

    // Independent predicated row loads (x is pre-launch data: __ldg OK).
    float4 v[FRAMES];
    #pragma unroll
    for (int j = 0; j < FRAMES; ++j) {
        v[j] = z;
        if (lead[j] && tok[j] >= 0) v[j] = __ldg(&x4[(size_t)tok[j] * LR_V4]);
    }
    #pragma unroll
    for (int j = 1; j < FRAMES; ++j) {
        if (!lead[j]) v[j] = v[j - 1];
    }
    #pragma unroll
    for (int j = 0; j < FRAMES; ++j) {
        __stcs(&o[(size_t)j * LR_V4], v[j]);
    }
}

extern "C" void kernel_launch(void* const* d_in, const int* in_sizes, int n_in,
                              void* d_out, int out_size) {
    const float* x   = (const float*)d_in[0];  // [B, T, D] fp32
    const int*   dur = (const int*)d_in[1];    // [B, T] int32
    float* out = (float*)d_out;

    const long long padded_elems = (long long)LR_B * LR_F * LR_D;
    float* dur_out =
        ((long long)out_size >= padded_elems + (long long)LR_B * LR_T)
            ? out + padded_elems : nullptr;

    lr_scan_kernel<<<LR_B, NTHR>>>(dur, dur_out);

    // Expand with Programmatic Dependent Launch.
    cudaLaunchConfig_t cfg = {};
    cfg.gridDim  = dim3(SLABS, LR_B);
    cfg.blockDim = dim3(LR_V4);
    cfg.stream   = 0;
    cudaLaunchAttribute attrs[1];
    attrs[0].id = cudaLaunchAttributeProgrammaticStreamSerialization;
    attrs[0].val.programmaticStreamSerializationAllowed = 1;
    cfg.attrs    = attrs;
    cfg.numAttrs = 1;
    cudaError_t err = cudaLaunchKernelEx(&cfg, lr_expand_kernel, x, out);
    if (err != cudaSuccess) {
        lr_expand_kernel<<<dim3(SLABS, LR_B), LR_V4>>>(x, out);
    }
}

// round 14
// speedup vs baseline: 1.0653x; 1.0653x over previous
#include <cuda_runtime.h>
#include <cuda_bf16.h>
#include <cstdint>

// LengthRegulator. Live work (predictor is dead code in the reference):
//   cum = cumsum(target_durations, axis=1)
//   padded[b,f,:] = (f < cum[b,-1]) ? x[b, upper_bound(cum[b], f), :] : 0
//   durations_out = target_durations
// B=8, T=1024, D=1024, F=8192. Output fp32: [B*F*D padded][B*T durations].
//
// R14: expand = exact R9 champion (44.1us). Prologue parallelized 8x:
// 64 scatter blocks, each redundantly recomputes its batch's scan (cheap)
// and scatters a 1/8 frame-slice. PDL trigger after the scatter.

#define LR_B 8
#define LR_T 1024
#define LR_D 1024
#define LR_F 8192
#define LR_V4 (LR_D / 4)          // 256 float4 per row
#define FRAMES 8                  // frames per expand block (uniform)
#define SLABS (LR_F / FRAMES)     // 1024 slabs per batch
#define NTHR 256
#define SLICES 8                  // scatter blocks per batch
#define SLICE_F (LR_F / SLICES)   // 1024 frames per scatter slice

__device__ int g_tok[LR_B * LR_F];   // frame -> token (-1 = invalid)

// ---------------------------------------------------------------------------
// Kernel 1: scan+scatter, 64 blocks. Block (b, slice): redundantly compute
// batch b's scan (256 thr x int4 + shuffles), scatter frames in
// [slice*1024, (slice+1)*1024). Slice 0 also writes durations out.
// ---------------------------------------------------------------------------
__global__ void __launch_bounds__(NTHR)
lr_scan_kernel(const int* __restrict__ dur, float* __restrict__ dur_out) {
    const int b     = blockIdx.x >> 3;
    const int slice = blockIdx.x & 7;
    const int tid   = threadIdx.x;
    __shared__ int warp_sums[8];
    __shared__ int s_total;

    const int4 dv = __ldg(reinterpret_cast<const int4*>(dur + b * LR_T) + tid);
    const int s0 = dv.x;
    const int s1 = s0 + dv.y;
    const int s2 = s1 + dv.z;
    const int s3 = s2 + dv.w;

    const int lane = tid & 31, wid = tid >> 5;
    int s = s3;
    #pragma unroll
    for (int o = 1; o < 32; o <<= 1) {
        int u = __shfl_up_sync(0xFFFFFFFFu, s, o);
        if (lane >= o) s += u;
    }
    if (lane == 31) warp_sums[wid] = s;
    __syncthreads();
    if (wid == 0 && lane < 8) {
        int ws = warp_sums[lane];
        #pragma unroll
        for (int o = 1; o < 8; o <<= 1) {
            int u = __shfl_up_sync(0xFFu, ws, o);
            if (lane >= o) ws += u;
        }
        warp_sums[lane] = ws;
    }
    __syncthreads();
    const int base = ((wid > 0) ? warp_sums[wid - 1] : 0) + s - s3;  // exclusive
    if (tid == NTHR - 1) s_total = base + s3;
    __syncthreads();
    const int total = s_total;

    const int lo = slice * SLICE_F;
    const int hi = lo + SLICE_F;

    if (slice == 0 && dur_out) {
        float4 fo = make_float4((float)dv.x, (float)dv.y,
                                (float)dv.z, (float)dv.w);
        reinterpret_cast<float4*>(dur_out + b * LR_T)[tid] = fo;
    }

    int* tokb = &g_tok[b * LR_F];

    // invalid frames within this slice
    const int inv0 = (total > lo) ? total : lo;
    for (int f = inv0 + tid; f < hi; f += NTHR) tokb[f] = -1;

    // scatter: token 4*tid+k owns [base+s_{k-1}, base+s_k) ∩ [lo, hi)
    const int t0 = tid * 4;
    int st = base;
    #pragma unroll
    for (int k = 0; k < 4; ++k) {
        const int en = base + ((k == 0) ? s0 : (k == 1) ? s1 : (k == 2) ? s2 : s3);
        int f  = (st > lo) ? st : lo;
        int fe = (en < hi) ? en : hi;
        for (; f < fe; ++f) tokb[f] = t0 + k;
        st = en;
    }

#if __CUDA_ARCH__ >= 900
    cudaTriggerProgrammaticLaunchCompletion();  // after all g_tok writes
#endif
}

// ---------------------------------------------------------------------------
// Kernel 2: balanced expand, dedup'd independent loads (exact R9 champion).
// ---------------------------------------------------------------------------
__global__ void __launch_bounds__(LR_V4)
lr_expand_kernel(const float* __restrict__ x, float* __restrict__ out) {
#if __CUDA_ARCH__ >= 900
    cudaGridDependencySynchronize();
#endif
    const int b  = blockIdx.y;
    const int f0 = blockIdx.x * FRAMES;
    const int i  = threadIdx.x;  // 0..255

    const int* tokp = &g_tok[b * LR_F + f0];
    int tok[FRAMES];
    #pragma unroll
    for (int j = 0; j < FRAMES; ++j) tok[j] = __ldg(&tokp[j]);

    const float4* x4 = reinterpret_cast<const float4*>(x) +
                       (size_t)b * LR_T * LR_V4 + i;
    float4* o = reinterpret_cast<float4*>(out) +
                ((size_t)b * LR_F + f0) * LR_V4 + i;

    const float4 z = make_float4(0.f, 0.f, 0.f, 0.f);

    bool lead[FRAMES];
    lead[0] = true;
    #pragma unroll
    for (int j = 1; j < FRAMES; ++j) lead[j] = (tok[j] != tok[j - 1]);

    float4 v[FRAMES];
    #pragma unroll
    for (int j = 0; j < FRAMES; ++j) {
        v[j] = z;
        if (lead[j] && tok[j] >= 0) v[j] = __ldg(&x4[(size_t)tok[j] * LR_V4]);
    }
    #pragma unroll
    for (int j = 1; j < FRAMES; ++j) {
        if (!lead[j]) v[j] = v[j - 1];
    }
    #pragma unroll
    for (int j = 0; j < FRAMES; ++j) {
        __stcs(&o[(size_t)j * LR_V4], v[j]);
    }
}

extern "C" void kernel_launch(void* const* d_in, const int* in_sizes, int n_in,
                              void* d_out, int out_size) {
    const float* x   = (const float*)d_in[0];  // [B, T, D] fp32
    const int*   dur = (const int*)d_in[1];    // [B, T] int32
    float* out = (float*)d_out;

    const long long padded_elems = (long long)LR_B * LR_F * LR_D;
    float* dur_out =
        ((long long)out_size >= padded_elems + (long long)LR_B * LR_T)
            ? out + padded_elems : nullptr;

    lr_scan_kernel<<<LR_B * SLICES, NTHR>>>(dur, dur_out);

    cudaLaunchConfig_t cfg = {};
    cfg.gridDim  = dim3(SLABS, LR_B);
    cfg.blockDim = dim3(LR_V4);
    cfg.stream   = 0;
    cudaLaunchAttribute attrs[1];
    attrs[0].id = cudaLaunchAttributeProgrammaticStreamSerialization;
    attrs[0].val.programmaticStreamSerializationAllowed = 1;
    cfg.attrs    = attrs;
    cfg.numAttrs = 1;
    cudaError_t err = cudaLaunchKernelEx(&cfg, lr_expand_kernel, x, out);
    if (err != cudaSuccess) {
        lr_expand_kernel<<<dim3(SLABS, LR_B), LR_V4>>>(x, out);
    }
}